// round 15
// baseline (speedup 1.0000x reference)
#include <cuda_runtime.h>
#include <cuda_fp16.h>
#include <cstdint>

// Problem constants
#define SQ     8192
#define DMODEL 1152
#define NH     16
#define DH     72
#define QKV3   3456
#define LCHUNK 1024
#define NCHUNK 8

// Scratch (device globals; no cudaMalloc allowed)
__device__ __half g_qkv_h[(size_t)SQ * QKV3];      // fp16 qkv GEMM output (V read from here)
__device__ __half g_hidden_h[(size_t)SQ * DMODEL];
__device__ __half g_qkvw_h[(size_t)QKV3 * DMODEL];
__device__ __half g_projw_h[(size_t)DMODEL * DMODEL];
__device__ __half g_q_h[(size_t)SQ * DMODEL];      // roped Q fp16, scaled by scl*log2(e)
__device__ __half g_k_h[(size_t)SQ * DMODEL];      // roped K fp16
__device__ __half g_attn_h[(size_t)SQ * DMODEL];   // attention output fp16

// ---------------------------------------------------------------------------
// common PTX helpers (cp.async .ca — known-good)
// ---------------------------------------------------------------------------
__device__ __forceinline__ uint32_t smem_u32(const void* p) {
    uint32_t a;
    asm("{ .reg .u64 t; cvta.to.shared.u64 t, %1; cvt.u32.u64 %0, t; }"
        : "=r"(a) : "l"(p));
    return a;
}
__device__ __forceinline__ void cp16(uint32_t dst, const void* src) {
    asm volatile("cp.async.ca.shared.global [%0], [%1], 16;"
                 :: "r"(dst), "l"(src));
}
__device__ __forceinline__ void cp_commit() {
    asm volatile("cp.async.commit_group;");
}
template <int N>
__device__ __forceinline__ void cp_wait() {
    asm volatile("cp.async.wait_group %0;" :: "n"(N));
}
__device__ __forceinline__ void ldmatrix4(uint32_t& r0, uint32_t& r1,
                                          uint32_t& r2, uint32_t& r3,
                                          uint32_t addr) {
    asm volatile("ldmatrix.sync.aligned.m8n8.x4.shared.b16 {%0,%1,%2,%3}, [%4];"
                 : "=r"(r0), "=r"(r1), "=r"(r2), "=r"(r3) : "r"(addr));
}
__device__ __forceinline__ void ldmatrix4_trans(uint32_t& r0, uint32_t& r1,
                                                uint32_t& r2, uint32_t& r3,
                                                uint32_t addr) {
    asm volatile("ldmatrix.sync.aligned.m8n8.x4.trans.shared.b16 {%0,%1,%2,%3}, [%4];"
                 : "=r"(r0), "=r"(r1), "=r"(r2), "=r"(r3) : "r"(addr));
}
__device__ __forceinline__ void mma16816(float& c0, float& c1, float& c2, float& c3,
                                         uint32_t a0, uint32_t a1, uint32_t a2, uint32_t a3,
                                         uint32_t b0, uint32_t b1) {
    asm volatile(
        "mma.sync.aligned.m16n8k16.row.col.f32.f16.f16.f32 "
        "{%0,%1,%2,%3}, {%4,%5,%6,%7}, {%8,%9}, {%0,%1,%2,%3};"
        : "+f"(c0), "+f"(c1), "+f"(c2), "+f"(c3)
        : "r"(a0), "r"(a1), "r"(a2), "r"(a3), "r"(b0), "r"(b1));
}
__device__ __forceinline__ uint32_t pack_h2(float lo, float hi) {
    uint32_t r;
    asm("cvt.rn.f16x2.f32 %0, %1, %2;" : "=r"(r) : "f"(hi), "f"(lo));
    return r;
}
__device__ __forceinline__ float ex2(float x) {
    float y;
    asm("ex2.approx.ftz.f32 %0, %1;" : "=f"(y) : "f"(x));
    return y;
}

// ---------------------------------------------------------------------------
// merged fp32 -> fp16 conversion over three buffers (one launch)
// ---------------------------------------------------------------------------
#define CVT_N1 (SQ * DMODEL)        // hidden     9437184
#define CVT_N2 (QKV3 * DMODEL)      // qkv_w      3981312
#define CVT_N3 (DMODEL * DMODEL)    // proj_w     1327104

__global__ __launch_bounds__(256) void cvt3_f16_kernel(
    const float* __restrict__ in1, __half* __restrict__ out1,
    const float* __restrict__ in2, __half* __restrict__ out2,
    const float* __restrict__ in3, __half* __restrict__ out3)
{
    int i = (blockIdx.x * blockDim.x + threadIdx.x) * 4;
    const float* in;
    __half* out;
    if (i < CVT_N1)                   { in = in1; out = out1; }
    else if (i < CVT_N1 + CVT_N2)     { in = in2; out = out2; i -= CVT_N1; }
    else if (i < CVT_N1 + CVT_N2 + CVT_N3) { in = in3; out = out3; i -= CVT_N1 + CVT_N2; }
    else return;
    const float4 v = *(const float4*)(in + i);
    __half2* o = (__half2*)(out + i);
    o[0] = __floats2half2_rn(v.x, v.y);
    o[1] = __floats2half2_rn(v.z, v.w);
}

// ---------------------------------------------------------------------------
// fp16 tensor-core GEMM (R14 known-good): C = A @ W^T + bias.
// 128x128 tile, BK=64, 2-stage cp.async, 256 threads, 144B smem rows,
// single barrier per slab.
// ---------------------------------------------------------------------------
#define BM 128
#define BN 128
#define BK 64
#define SROW 144
#define G_STAGE (BM * SROW)
#define GSM_BYTES (4 * G_STAGE)

template <typename OutT>
__global__ __launch_bounds__(256) void gemm_f16_kernel(
    const __half* __restrict__ A, const __half* __restrict__ W,
    const float* __restrict__ bias, OutT* __restrict__ C,
    int M, int N, int K)
{
    extern __shared__ unsigned char gsm[];
    const uint32_t sA = smem_u32(gsm);
    const uint32_t sB = sA + 2 * G_STAGE;

    const int tid  = threadIdx.x;
    const int wid  = tid >> 5;
    const int lane = tid & 31;
    const int bm = blockIdx.y * BM;
    const int bn = blockIdx.x * BN;

    const int warp_m = (wid >> 2) * 64;
    const int warp_n = (wid & 3) * 32;

    const int nslab = K / BK;

    auto load_stage = [&](int buf, int k0) {
#pragma unroll
        for (int u = 0; u < 4; u++) {
            const int c = tid + u * 256;
            const int row = c >> 3, col = c & 7;
            cp16(sA + buf * G_STAGE + row * SROW + col * 16,
                 A + (size_t)(bm + row) * K + k0 + col * 8);
            cp16(sB + buf * G_STAGE + row * SROW + col * 16,
                 W + (size_t)(bn + row) * K + k0 + col * 8);
        }
        cp_commit();
    };

    load_stage(0, 0);

    float acc[4][4][4];
#pragma unroll
    for (int i = 0; i < 4; i++)
#pragma unroll
        for (int j = 0; j < 4; j++)
#pragma unroll
            for (int v = 0; v < 4; v++) acc[i][j][v] = 0.f;

    const int a_row = lane & 15;
    const int a_kof = (lane >> 4) * 8;
    const int b_row = ((lane >> 4) * 8) + (lane & 7);
    const int b_kof = ((lane >> 3) & 1) * 8;

    for (int s = 0; s < nslab; s++) {
        const int buf = s & 1;
        cp_wait<0>();
        __syncthreads();

        if (s + 1 < nslab)
            load_stage((s + 1) & 1, (s + 1) * BK);

        const uint32_t bA = sA + buf * G_STAGE;
        const uint32_t bB = sB + buf * G_STAGE;

#pragma unroll
        for (int ks = 0; ks < 4; ks++) {
            uint32_t af[4][4];
#pragma unroll
            for (int mt = 0; mt < 4; mt++)
                ldmatrix4(af[mt][0], af[mt][1], af[mt][2], af[mt][3],
                          bA + (warp_m + mt * 16 + a_row) * SROW
                             + (ks * 16 + a_kof) * 2);
            uint32_t bf[4][2];
#pragma unroll
            for (int nt2 = 0; nt2 < 2; nt2++) {
                uint32_t r0, r1, r2, r3;
                ldmatrix4(r0, r1, r2, r3,
                          bB + (warp_n + nt2 * 16 + b_row) * SROW
                             + (ks * 16 + b_kof) * 2);
                bf[nt2 * 2 + 0][0] = r0; bf[nt2 * 2 + 0][1] = r1;
                bf[nt2 * 2 + 1][0] = r2; bf[nt2 * 2 + 1][1] = r3;
            }
#pragma unroll
            for (int mt = 0; mt < 4; mt++)
#pragma unroll
                for (int nt = 0; nt < 4; nt++)
                    mma16816(acc[mt][nt][0], acc[mt][nt][1],
                             acc[mt][nt][2], acc[mt][nt][3],
                             af[mt][0], af[mt][1], af[mt][2], af[mt][3],
                             bf[nt][0], bf[nt][1]);
        }
    }

    const int erow = lane >> 2;
    const int ecol = (lane & 3) * 2;
#pragma unroll
    for (int mt = 0; mt < 4; mt++) {
#pragma unroll
        for (int nt = 0; nt < 4; nt++) {
            const int col = bn + warp_n + nt * 8 + ecol;
            const float b0 = bias[col], b1 = bias[col + 1];
            const size_t r0 = (size_t)(bm + warp_m + mt * 16 + erow);
            if constexpr (sizeof(OutT) == 2) {
                *(uint32_t*)((__half*)C + r0 * N + col) =
                    pack_h2(acc[mt][nt][0] + b0, acc[mt][nt][1] + b1);
                *(uint32_t*)((__half*)C + (r0 + 8) * N + col) =
                    pack_h2(acc[mt][nt][2] + b0, acc[mt][nt][3] + b1);
            } else {
                *(float2*)((float*)C + r0 * N + col) =
                    make_float2(acc[mt][nt][0] + b0, acc[mt][nt][1] + b1);
                *(float2*)((float*)C + (r0 + 8) * N + col) =
                    make_float2(acc[mt][nt][2] + b0, acc[mt][nt][3] + b1);
            }
        }
    }
}

// ---------------------------------------------------------------------------
// RoPE: Q scaled by (1/sqrt(DH)) * log2(e); K unscaled. V untouched.
// ---------------------------------------------------------------------------
__global__ __launch_bounds__(256) void rope_pack_kernel(
    const __half* __restrict__ qkv, const float* __restrict__ cosp,
    const float* __restrict__ sinp,
    __half* __restrict__ qh, __half* __restrict__ kh)
{
    const int idx = blockIdx.x * blockDim.x + threadIdx.x;
    const int total = SQ * NH * (DH / 2);
    if (idx >= total) return;
    const int d = idx % (DH / 2);
    const int t = idx / (DH / 2);
    const int h = t % NH;
    const int s = t / NH;

    const float c1 = cosp[s * DH + d];
    const float s1 = sinp[s * DH + d];
    const float c2 = cosp[s * DH + d + 36];
    const float s2 = sinp[s * DH + d + 36];
    const float scl = rsqrtf((float)DH) * 1.4426950408889634f;  // fold log2(e)

    const size_t base = (size_t)s * QKV3 + h * DH;
    {
        const float x1 = __half2float(qkv[base + d]);
        const float x2 = __half2float(qkv[base + d + 36]);
        qh[(size_t)s * DMODEL + h * DH + d]      = __float2half_rn((x1 * c1 - x2 * s1) * scl);
        qh[(size_t)s * DMODEL + h * DH + d + 36] = __float2half_rn((x2 * c2 + x1 * s2) * scl);
    }
    {
        const float x1 = __half2float(qkv[base + DMODEL + d]);
        const float x2 = __half2float(qkv[base + DMODEL + d + 36]);
        kh[(size_t)s * DMODEL + h * DH + d]      = __float2half_rn(x1 * c1 - x2 * s1);
        kh[(size_t)s * DMODEL + h * DH + d + 36] = __float2half_rn(x2 * c2 + x1 * s2);
    }
}

// ---------------------------------------------------------------------------
// Tensor-core flash attention (R14 structure), PERSISTENT CTAs:
// grid = 2*SM_count blocks, each loops over work items (qt, chh) to kill
// the 3.46-wave quantization tail. Item order keeps same-chh blocks adjacent
// for K/V L2 locality. Per-item math identical to R14.
// smem: sQ 128x176 + sK 2x64x176 + sV 2x64x176 = 67584 B.
// ---------------------------------------------------------------------------
#define AQ_ROWB  176
#define A_SQ_OFF  0
#define A_SK_OFF  (128 * AQ_ROWB)                 // 22528
#define A_SK_SZ   (64 * AQ_ROWB)                  // 11264
#define A_SV_OFF  (A_SK_OFF + 2 * A_SK_SZ)        // 45056
#define A_SV_SZ   (64 * AQ_ROWB)                  // 11264
#define A_SMEM_BYTES (A_SV_OFF + 2 * A_SV_SZ)     // 67584
#define A_NITEM  (8 * NCHUNK * NH)                // 1024 work items

__global__ __launch_bounds__(256) void attn_mma_kernel(
    const __half* __restrict__ Qg, const __half* __restrict__ Kg,
    const __half* __restrict__ qkv, __half* __restrict__ out)
{
    extern __shared__ unsigned char asmem[];
    const uint32_t sb = smem_u32(asmem);
    const int tid  = threadIdx.x;
    const int wid  = tid >> 5;
    const int lane = tid & 31;
    const int warp_m = wid * 16;

    // ---- zero pads once (loads never touch columns 144..159) ----
    const uint4 z4 = make_uint4(0, 0, 0, 0);
    if (tid < 128) {
        *(uint4*)(asmem + A_SQ_OFF + tid * AQ_ROWB + 144) = z4;
        const int buf = tid >> 6, row = tid & 63;
        *(uint4*)(asmem + A_SK_OFF + buf * A_SK_SZ + row * AQ_ROWB + 144) = z4;
    } else {
        const int t = tid - 128;
        const int buf = t >> 6, row = t & 63;
        *(uint4*)(asmem + A_SV_OFF + buf * A_SV_SZ + row * AQ_ROWB + 144) = z4;
    }

    const int a_row = lane & 15;
    const int a_kof = (lane >> 4) * 8;
    const int b_row = ((lane >> 4) * 8) + (lane & 7);
    const int b_kof = ((lane >> 3) & 1) * 8;
    const int tv_row = ((lane >> 3) & 1) * 8 + (lane & 7);
    const int tv_n   = (lane >> 4) * 8;

    const int NTILE = LCHUNK / 64;   // 16

    for (int item = blockIdx.x; item < A_NITEM; item += gridDim.x) {
        const int qt  = item & 7;
        const int chh = item >> 3;
        const int chunk = chh >> 4, h = chh & 15;
        const size_t rowbase = (size_t)chunk * LCHUNK;
        const int q0 = qt * 128;
        const __half* Vg = qkv + 2 * DMODEL + h * DH;

        // loader for one 64-key tile
        auto load_tile = [&](int nbuf, int k0) {
            for (int i = tid; i < 1152; i += 256) {
                if (i < 576) {
                    const int row = i / 9, c = i % 9;
                    cp16(sb + A_SK_OFF + nbuf * A_SK_SZ + row * AQ_ROWB + c * 16,
                         Kg + (rowbase + k0 + row) * DMODEL + h * DH + c * 8);
                } else {
                    const int j = i - 576;
                    const int row = j / 9, c = j % 9;
                    cp16(sb + A_SV_OFF + nbuf * A_SV_SZ + row * AQ_ROWB + c * 16,
                         Vg + (rowbase + k0 + row) * QKV3 + c * 8);
                }
            }
            cp_commit();
        };

        // prologue: Q tile + key tile 0 (one group)
        for (int i = tid; i < 128 * 9; i += 256) {
            const int row = i / 9, c = i % 9;
            cp16(sb + A_SQ_OFF + row * AQ_ROWB + c * 16,
                 Qg + (rowbase + q0 + row) * DMODEL + h * DH + c * 8);
        }
        load_tile(0, 0);

        uint32_t qf[5][4];
        float oacc[9][4];
#pragma unroll
        for (int i = 0; i < 9; i++)
#pragma unroll
            for (int j = 0; j < 4; j++) oacc[i][j] = 0.f;
        float l0 = 0.f, l1 = 0.f;

        for (int t = 0; t < NTILE; t++) {
            const int buf = t & 1;
            cp_wait<0>();
            __syncthreads();

            if (t + 1 < NTILE)
                load_tile((t + 1) & 1, (t + 1) * 64);

            if (t == 0) {
#pragma unroll
                for (int kt = 0; kt < 5; kt++)
                    ldmatrix4(qf[kt][0], qf[kt][1], qf[kt][2], qf[kt][3],
                              sb + A_SQ_OFF + (warp_m + a_row) * AQ_ROWB
                                 + (kt * 16 + a_kof) * 2);
            }

            const uint32_t bK = sb + A_SK_OFF + buf * A_SK_SZ;
            const uint32_t bV = sb + A_SV_OFF + buf * A_SV_SZ;

            float sacc[8][4];
#pragma unroll
            for (int i = 0; i < 8; i++)
#pragma unroll
                for (int j = 0; j < 4; j++) sacc[i][j] = 0.f;

#pragma unroll
            for (int kt = 0; kt < 5; kt++) {
#pragma unroll
                for (int bp = 0; bp < 4; bp++) {
                    uint32_t r0, r1, r2, r3;
                    ldmatrix4(r0, r1, r2, r3,
                              bK + (bp * 16 + b_row) * AQ_ROWB + (kt * 16 + b_kof) * 2);
                    mma16816(sacc[2 * bp][0], sacc[2 * bp][1],
                             sacc[2 * bp][2], sacc[2 * bp][3],
                             qf[kt][0], qf[kt][1], qf[kt][2], qf[kt][3], r0, r1);
                    mma16816(sacc[2 * bp + 1][0], sacc[2 * bp + 1][1],
                             sacc[2 * bp + 1][2], sacc[2 * bp + 1][3],
                             qf[kt][0], qf[kt][1], qf[kt][2], qf[kt][3], r2, r3);
                }
            }

            uint32_t pf[4][4];
#pragma unroll
            for (int i = 0; i < 8; i++) {
                sacc[i][0] = ex2(sacc[i][0]);
                sacc[i][1] = ex2(sacc[i][1]);
                sacc[i][2] = ex2(sacc[i][2]);
                sacc[i][3] = ex2(sacc[i][3]);
                l0 += sacc[i][0] + sacc[i][1];
                l1 += sacc[i][2] + sacc[i][3];
            }
#pragma unroll
            for (int kt = 0; kt < 4; kt++) {
                pf[kt][0] = pack_h2(sacc[2 * kt][0],     sacc[2 * kt][1]);
                pf[kt][1] = pack_h2(sacc[2 * kt][2],     sacc[2 * kt][3]);
                pf[kt][2] = pack_h2(sacc[2 * kt + 1][0], sacc[2 * kt + 1][1]);
                pf[kt][3] = pack_h2(sacc[2 * kt + 1][2], sacc[2 * kt + 1][3]);
            }

#pragma unroll
            for (int kt = 0; kt < 4; kt++) {
#pragma unroll
                for (int bp = 0; bp < 5; bp++) {
                    uint32_t r0, r1, r2, r3;
                    ldmatrix4_trans(r0, r1, r2, r3,
                                    bV + (kt * 16 + tv_row) * AQ_ROWB
                                       + (bp * 16 + tv_n) * 2);
                    mma16816(oacc[2 * bp][0], oacc[2 * bp][1],
                             oacc[2 * bp][2], oacc[2 * bp][3],
                             pf[kt][0], pf[kt][1], pf[kt][2], pf[kt][3], r0, r1);
                    if (bp < 4)
                        mma16816(oacc[2 * bp + 1][0], oacc[2 * bp + 1][1],
                                 oacc[2 * bp + 1][2], oacc[2 * bp + 1][3],
                                 pf[kt][0], pf[kt][1], pf[kt][2], pf[kt][3], r2, r3);
                }
            }
        }

        // epilogue
        l0 += __shfl_xor_sync(0xffffffffu, l0, 1);
        l0 += __shfl_xor_sync(0xffffffffu, l0, 2);
        l1 += __shfl_xor_sync(0xffffffffu, l1, 1);
        l1 += __shfl_xor_sync(0xffffffffu, l1, 2);
        const float inv0 = 1.f / l0;
        const float inv1 = 1.f / l1;
        const int r = lane >> 2;
        const size_t row0 = rowbase + q0 + warp_m + r;
        const int colb = h * DH + (lane & 3) * 2;
#pragma unroll
        for (int i = 0; i < 9; i++) {
            const int col = colb + i * 8;
            *(uint32_t*)(out + row0 * DMODEL + col) =
                pack_h2(oacc[i][0] * inv0, oacc[i][1] * inv0);
            *(uint32_t*)(out + (row0 + 8) * DMODEL + col) =
                pack_h2(oacc[i][2] * inv1, oacc[i][3] * inv1);
        }

        __syncthreads();   // slowest warp done reading smem before next item loads
    }
}

// ---------------------------------------------------------------------------
// kernel_launch
// ---------------------------------------------------------------------------
extern "C" void kernel_launch(void* const* d_in, const int* in_sizes, int n_in,
                              void* d_out, int out_size)
{
    const float* hidden = (const float*)d_in[0];
    const float* cosp   = (const float*)d_in[1];
    const float* sinp   = (const float*)d_in[2];
    const float* qkv_w  = (const float*)d_in[3];
    const float* qkv_b  = (const float*)d_in[4];
    const float* proj_w = (const float*)d_in[5];
    const float* proj_b = (const float*)d_in[6];
    (void)in_sizes; (void)n_in;

    __half *qkv_h = nullptr, *hidden_h = nullptr, *qkvw_h = nullptr, *projw_h = nullptr;
    __half *qh = nullptr, *kh = nullptr, *attn_h = nullptr;
    cudaGetSymbolAddress((void**)&qkv_h, g_qkv_h);
    cudaGetSymbolAddress((void**)&hidden_h, g_hidden_h);
    cudaGetSymbolAddress((void**)&qkvw_h, g_qkvw_h);
    cudaGetSymbolAddress((void**)&projw_h, g_projw_h);
    cudaGetSymbolAddress((void**)&qh, g_q_h);
    cudaGetSymbolAddress((void**)&kh, g_k_h);
    cudaGetSymbolAddress((void**)&attn_h, g_attn_h);

    static int sm_count = 0;
    if (sm_count == 0) {
        cudaDeviceGetAttribute(&sm_count, cudaDevAttrMultiProcessorCount, 0);
        if (sm_count <= 0) sm_count = 148;
    }

    cudaFuncSetAttribute(gemm_f16_kernel<__half>,
                         cudaFuncAttributeMaxDynamicSharedMemorySize, GSM_BYTES);
    cudaFuncSetAttribute(gemm_f16_kernel<float>,
                         cudaFuncAttributeMaxDynamicSharedMemorySize, GSM_BYTES);
    cudaFuncSetAttribute(attn_mma_kernel,
                         cudaFuncAttributeMaxDynamicSharedMemorySize, A_SMEM_BYTES);

    // 0) fp32 -> fp16 conversions (single launch)
    {
        const int ntot = CVT_N1 + CVT_N2 + CVT_N3;
        cvt3_f16_kernel<<<(ntot / 4 + 255) / 256, 256>>>(
            hidden, hidden_h, qkv_w, qkvw_h, proj_w, projw_h);
    }

    // 1) QKV GEMM + bias -> fp16
    gemm_f16_kernel<__half><<<dim3(QKV3 / BN, SQ / BM), 256, GSM_BYTES>>>(
        hidden_h, qkvw_h, qkv_b, qkv_h, SQ, QKV3, DMODEL);

    // 2) RoPE (Q scaled incl. log2e, K) — V untouched
    {
        const int total = SQ * NH * (DH / 2);
        rope_pack_kernel<<<(total + 255) / 256, 256>>>(qkv_h, cosp, sinp, qh, kh);
    }

    // 3) persistent tensor-core flash attention
    attn_mma_kernel<<<2 * sm_count, 256, A_SMEM_BYTES>>>(qh, kh, qkv_h, attn_h);

    // 4) output projection + bias -> fp32 d_out
    gemm_f16_kernel<float><<<dim3(DMODEL / BN, SQ / BM), 256, GSM_BYTES>>>(
        attn_h, projw_h, proj_b, (float*)d_out, SQ, DMODEL, DMODEL);
}

// round 16
// speedup vs baseline: 1.0155x; 1.0155x over previous
#include <cuda_runtime.h>
#include <cuda_fp16.h>
#include <cstdint>

// Problem constants
#define SQ     8192
#define DMODEL 1152
#define NH     16
#define DH     72
#define QKV3   3456
#define LCHUNK 1024
#define NCHUNK 8

// Scratch (device globals; no cudaMalloc allowed)
__device__ __half g_qkv_h[(size_t)SQ * QKV3];      // fp16 qkv GEMM output (V read from here)
__device__ __half g_hidden_h[(size_t)SQ * DMODEL];
__device__ __half g_qkvw_h[(size_t)QKV3 * DMODEL];
__device__ __half g_projw_h[(size_t)DMODEL * DMODEL];
__device__ __half g_q_h[(size_t)SQ * DMODEL];      // roped Q fp16, scaled by scl*log2(e)
__device__ __half g_k_h[(size_t)SQ * DMODEL];      // roped K fp16
__device__ __half g_attn_h[(size_t)SQ * DMODEL];   // attention output fp16

// ---------------------------------------------------------------------------
// common PTX helpers (cp.async .ca — known-good)
// ---------------------------------------------------------------------------
__device__ __forceinline__ uint32_t smem_u32(const void* p) {
    uint32_t a;
    asm("{ .reg .u64 t; cvta.to.shared.u64 t, %1; cvt.u32.u64 %0, t; }"
        : "=r"(a) : "l"(p));
    return a;
}
__device__ __forceinline__ void cp16(uint32_t dst, const void* src) {
    asm volatile("cp.async.ca.shared.global [%0], [%1], 16;"
                 :: "r"(dst), "l"(src));
}
__device__ __forceinline__ void cp_commit() {
    asm volatile("cp.async.commit_group;");
}
template <int N>
__device__ __forceinline__ void cp_wait() {
    asm volatile("cp.async.wait_group %0;" :: "n"(N));
}
__device__ __forceinline__ void ldmatrix4(uint32_t& r0, uint32_t& r1,
                                          uint32_t& r2, uint32_t& r3,
                                          uint32_t addr) {
    asm volatile("ldmatrix.sync.aligned.m8n8.x4.shared.b16 {%0,%1,%2,%3}, [%4];"
                 : "=r"(r0), "=r"(r1), "=r"(r2), "=r"(r3) : "r"(addr));
}
__device__ __forceinline__ void ldmatrix4_trans(uint32_t& r0, uint32_t& r1,
                                                uint32_t& r2, uint32_t& r3,
                                                uint32_t addr) {
    asm volatile("ldmatrix.sync.aligned.m8n8.x4.trans.shared.b16 {%0,%1,%2,%3}, [%4];"
                 : "=r"(r0), "=r"(r1), "=r"(r2), "=r"(r3) : "r"(addr));
}
__device__ __forceinline__ void mma16816(float& c0, float& c1, float& c2, float& c3,
                                         uint32_t a0, uint32_t a1, uint32_t a2, uint32_t a3,
                                         uint32_t b0, uint32_t b1) {
    asm volatile(
        "mma.sync.aligned.m16n8k16.row.col.f32.f16.f16.f32 "
        "{%0,%1,%2,%3}, {%4,%5,%6,%7}, {%8,%9}, {%0,%1,%2,%3};"
        : "+f"(c0), "+f"(c1), "+f"(c2), "+f"(c3)
        : "r"(a0), "r"(a1), "r"(a2), "r"(a3), "r"(b0), "r"(b1));
}
__device__ __forceinline__ uint32_t pack_h2(float lo, float hi) {
    uint32_t r;
    asm("cvt.rn.f16x2.f32 %0, %1, %2;" : "=r"(r) : "f"(hi), "f"(lo));
    return r;
}
__device__ __forceinline__ float ex2(float x) {
    float y;
    asm("ex2.approx.ftz.f32 %0, %1;" : "=f"(y) : "f"(x));
    return y;
}

// ---------------------------------------------------------------------------
// merged fp32 -> fp16 conversion over three buffers (one launch)
// ---------------------------------------------------------------------------
#define CVT_N1 (SQ * DMODEL)        // hidden     9437184
#define CVT_N2 (QKV3 * DMODEL)      // qkv_w      3981312
#define CVT_N3 (DMODEL * DMODEL)    // proj_w     1327104

__global__ __launch_bounds__(256) void cvt3_f16_kernel(
    const float* __restrict__ in1, __half* __restrict__ out1,
    const float* __restrict__ in2, __half* __restrict__ out2,
    const float* __restrict__ in3, __half* __restrict__ out3)
{
    int i = (blockIdx.x * blockDim.x + threadIdx.x) * 4;
    const float* in;
    __half* out;
    if (i < CVT_N1)                   { in = in1; out = out1; }
    else if (i < CVT_N1 + CVT_N2)     { in = in2; out = out2; i -= CVT_N1; }
    else if (i < CVT_N1 + CVT_N2 + CVT_N3) { in = in3; out = out3; i -= CVT_N1 + CVT_N2; }
    else return;
    const float4 v = *(const float4*)(in + i);
    __half2* o = (__half2*)(out + i);
    o[0] = __floats2half2_rn(v.x, v.y);
    o[1] = __floats2half2_rn(v.z, v.w);
}

// ---------------------------------------------------------------------------
// fp16 tensor-core GEMM (R14 known-good): C = A @ W^T + bias.
// 128x128 tile, BK=64, 2-stage cp.async, 256 threads, 144B smem rows,
// single barrier per slab.
// ---------------------------------------------------------------------------
#define BM 128
#define BN 128
#define BK 64
#define SROW 144
#define G_STAGE (BM * SROW)
#define GSM_BYTES (4 * G_STAGE)

template <typename OutT>
__global__ __launch_bounds__(256) void gemm_f16_kernel(
    const __half* __restrict__ A, const __half* __restrict__ W,
    const float* __restrict__ bias, OutT* __restrict__ C,
    int M, int N, int K)
{
    extern __shared__ unsigned char gsm[];
    const uint32_t sA = smem_u32(gsm);
    const uint32_t sB = sA + 2 * G_STAGE;

    const int tid  = threadIdx.x;
    const int wid  = tid >> 5;
    const int lane = tid & 31;
    const int bm = blockIdx.y * BM;
    const int bn = blockIdx.x * BN;

    const int warp_m = (wid >> 2) * 64;
    const int warp_n = (wid & 3) * 32;

    const int nslab = K / BK;

    auto load_stage = [&](int buf, int k0) {
#pragma unroll
        for (int u = 0; u < 4; u++) {
            const int c = tid + u * 256;
            const int row = c >> 3, col = c & 7;
            cp16(sA + buf * G_STAGE + row * SROW + col * 16,
                 A + (size_t)(bm + row) * K + k0 + col * 8);
            cp16(sB + buf * G_STAGE + row * SROW + col * 16,
                 W + (size_t)(bn + row) * K + k0 + col * 8);
        }
        cp_commit();
    };

    load_stage(0, 0);

    float acc[4][4][4];
#pragma unroll
    for (int i = 0; i < 4; i++)
#pragma unroll
        for (int j = 0; j < 4; j++)
#pragma unroll
            for (int v = 0; v < 4; v++) acc[i][j][v] = 0.f;

    const int a_row = lane & 15;
    const int a_kof = (lane >> 4) * 8;
    const int b_row = ((lane >> 4) * 8) + (lane & 7);
    const int b_kof = ((lane >> 3) & 1) * 8;

    for (int s = 0; s < nslab; s++) {
        const int buf = s & 1;
        cp_wait<0>();
        __syncthreads();

        if (s + 1 < nslab)
            load_stage((s + 1) & 1, (s + 1) * BK);

        const uint32_t bA = sA + buf * G_STAGE;
        const uint32_t bB = sB + buf * G_STAGE;

#pragma unroll
        for (int ks = 0; ks < 4; ks++) {
            uint32_t af[4][4];
#pragma unroll
            for (int mt = 0; mt < 4; mt++)
                ldmatrix4(af[mt][0], af[mt][1], af[mt][2], af[mt][3],
                          bA + (warp_m + mt * 16 + a_row) * SROW
                             + (ks * 16 + a_kof) * 2);
            uint32_t bf[4][2];
#pragma unroll
            for (int nt2 = 0; nt2 < 2; nt2++) {
                uint32_t r0, r1, r2, r3;
                ldmatrix4(r0, r1, r2, r3,
                          bB + (warp_n + nt2 * 16 + b_row) * SROW
                             + (ks * 16 + b_kof) * 2);
                bf[nt2 * 2 + 0][0] = r0; bf[nt2 * 2 + 0][1] = r1;
                bf[nt2 * 2 + 1][0] = r2; bf[nt2 * 2 + 1][1] = r3;
            }
#pragma unroll
            for (int mt = 0; mt < 4; mt++)
#pragma unroll
                for (int nt = 0; nt < 4; nt++)
                    mma16816(acc[mt][nt][0], acc[mt][nt][1],
                             acc[mt][nt][2], acc[mt][nt][3],
                             af[mt][0], af[mt][1], af[mt][2], af[mt][3],
                             bf[nt][0], bf[nt][1]);
        }
    }

    const int erow = lane >> 2;
    const int ecol = (lane & 3) * 2;
#pragma unroll
    for (int mt = 0; mt < 4; mt++) {
#pragma unroll
        for (int nt = 0; nt < 4; nt++) {
            const int col = bn + warp_n + nt * 8 + ecol;
            const float b0 = bias[col], b1 = bias[col + 1];
            const size_t r0 = (size_t)(bm + warp_m + mt * 16 + erow);
            if constexpr (sizeof(OutT) == 2) {
                *(uint32_t*)((__half*)C + r0 * N + col) =
                    pack_h2(acc[mt][nt][0] + b0, acc[mt][nt][1] + b1);
                *(uint32_t*)((__half*)C + (r0 + 8) * N + col) =
                    pack_h2(acc[mt][nt][2] + b0, acc[mt][nt][3] + b1);
            } else {
                *(float2*)((float*)C + r0 * N + col) =
                    make_float2(acc[mt][nt][0] + b0, acc[mt][nt][1] + b1);
                *(float2*)((float*)C + (r0 + 8) * N + col) =
                    make_float2(acc[mt][nt][2] + b0, acc[mt][nt][3] + b1);
            }
        }
    }
}

// ---------------------------------------------------------------------------
// RoPE: Q scaled by (1/sqrt(DH)) * log2(e); K unscaled. V untouched.
// ---------------------------------------------------------------------------
__global__ __launch_bounds__(256) void rope_pack_kernel(
    const __half* __restrict__ qkv, const float* __restrict__ cosp,
    const float* __restrict__ sinp,
    __half* __restrict__ qh, __half* __restrict__ kh)
{
    const int idx = blockIdx.x * blockDim.x + threadIdx.x;
    const int total = SQ * NH * (DH / 2);
    if (idx >= total) return;
    const int d = idx % (DH / 2);
    const int t = idx / (DH / 2);
    const int h = t % NH;
    const int s = t / NH;

    const float c1 = cosp[s * DH + d];
    const float s1 = sinp[s * DH + d];
    const float c2 = cosp[s * DH + d + 36];
    const float s2 = sinp[s * DH + d + 36];
    const float scl = rsqrtf((float)DH) * 1.4426950408889634f;  // fold log2(e)

    const size_t base = (size_t)s * QKV3 + h * DH;
    {
        const float x1 = __half2float(qkv[base + d]);
        const float x2 = __half2float(qkv[base + d + 36]);
        qh[(size_t)s * DMODEL + h * DH + d]      = __float2half_rn((x1 * c1 - x2 * s1) * scl);
        qh[(size_t)s * DMODEL + h * DH + d + 36] = __float2half_rn((x2 * c2 + x1 * s2) * scl);
    }
    {
        const float x1 = __half2float(qkv[base + DMODEL + d]);
        const float x2 = __half2float(qkv[base + DMODEL + d + 36]);
        kh[(size_t)s * DMODEL + h * DH + d]      = __float2half_rn(x1 * c1 - x2 * s1);
        kh[(size_t)s * DMODEL + h * DH + d + 36] = __float2half_rn(x2 * c2 + x1 * s2);
    }
}

// ---------------------------------------------------------------------------
// Tensor-core flash attention (exact R14 known-good): plain 1024-block grid,
// 256 threads, 128 q-rows/block, 64-key tiles, single barrier per tile,
// max-free softmax, V row-major via ldmatrix.trans.
// smem: sQ 128x176 + sK 2x64x176 + sV 2x64x176 = 67584 B.
// ---------------------------------------------------------------------------
#define AQ_ROWB  176
#define A_SQ_OFF  0
#define A_SK_OFF  (128 * AQ_ROWB)                 // 22528
#define A_SK_SZ   (64 * AQ_ROWB)                  // 11264
#define A_SV_OFF  (A_SK_OFF + 2 * A_SK_SZ)        // 45056
#define A_SV_SZ   (64 * AQ_ROWB)                  // 11264
#define A_SMEM_BYTES (A_SV_OFF + 2 * A_SV_SZ)     // 67584

__global__ __launch_bounds__(256) void attn_mma_kernel(
    const __half* __restrict__ Qg, const __half* __restrict__ Kg,
    const __half* __restrict__ qkv, __half* __restrict__ out)
{
    extern __shared__ unsigned char asmem[];
    const uint32_t sb = smem_u32(asmem);
    const int tid  = threadIdx.x;
    const int wid  = tid >> 5;
    const int lane = tid & 31;
    const int qt  = blockIdx.x;
    const int chh = blockIdx.y;
    const int chunk = chh >> 4, h = chh & 15;
    const size_t rowbase = (size_t)chunk * LCHUNK;
    const int q0 = qt * 128;
    const int warp_m = wid * 16;

    // V source: [S, 3, H, DH] slab 2
    const __half* Vg = qkv + 2 * DMODEL + h * DH;

    // ---- zero pads (d columns 72..79 of sQ, sK, sV) ----
    const uint4 z4 = make_uint4(0, 0, 0, 0);
    if (tid < 128) {
        *(uint4*)(asmem + A_SQ_OFF + tid * AQ_ROWB + 144) = z4;
        const int buf = tid >> 6, row = tid & 63;
        *(uint4*)(asmem + A_SK_OFF + buf * A_SK_SZ + row * AQ_ROWB + 144) = z4;
    } else {
        const int t = tid - 128;
        const int buf = t >> 6, row = t & 63;
        *(uint4*)(asmem + A_SV_OFF + buf * A_SV_SZ + row * AQ_ROWB + 144) = z4;
    }

    // loader for one 64-key tile: K 576 + V 576 chunks
    auto load_tile = [&](int nbuf, int k0) {
        for (int i = tid; i < 1152; i += 256) {
            if (i < 576) {
                const int row = i / 9, c = i % 9;
                cp16(sb + A_SK_OFF + nbuf * A_SK_SZ + row * AQ_ROWB + c * 16,
                     Kg + (rowbase + k0 + row) * DMODEL + h * DH + c * 8);
            } else {
                const int j = i - 576;
                const int row = j / 9, c = j % 9;
                cp16(sb + A_SV_OFF + nbuf * A_SV_SZ + row * AQ_ROWB + c * 16,
                     Vg + (rowbase + k0 + row) * QKV3 + c * 8);
            }
        }
        cp_commit();
    };

    // ---- prologue: Q tile + key tile 0 (one group) ----
    for (int i = tid; i < 128 * 9; i += 256) {
        const int row = i / 9, c = i % 9;
        cp16(sb + A_SQ_OFF + row * AQ_ROWB + c * 16,
             Qg + (rowbase + q0 + row) * DMODEL + h * DH + c * 8);
    }
    load_tile(0, 0);

    const int a_row = lane & 15;
    const int a_kof = (lane >> 4) * 8;
    const int b_row = ((lane >> 4) * 8) + (lane & 7);
    const int b_kof = ((lane >> 3) & 1) * 8;
    const int tv_row = ((lane >> 3) & 1) * 8 + (lane & 7);
    const int tv_n   = (lane >> 4) * 8;

    uint32_t qf[5][4];
    float oacc[9][4];
#pragma unroll
    for (int i = 0; i < 9; i++)
#pragma unroll
        for (int j = 0; j < 4; j++) oacc[i][j] = 0.f;
    float l0 = 0.f, l1 = 0.f;

    const int NTILE = LCHUNK / 64;   // 16

    for (int t = 0; t < NTILE; t++) {
        const int buf = t & 1;
        cp_wait<0>();
        __syncthreads();

        if (t + 1 < NTILE)
            load_tile((t + 1) & 1, (t + 1) * 64);

        if (t == 0) {
#pragma unroll
            for (int kt = 0; kt < 5; kt++)
                ldmatrix4(qf[kt][0], qf[kt][1], qf[kt][2], qf[kt][3],
                          sb + A_SQ_OFF + (warp_m + a_row) * AQ_ROWB
                             + (kt * 16 + a_kof) * 2);
        }

        const uint32_t bK = sb + A_SK_OFF + buf * A_SK_SZ;
        const uint32_t bV = sb + A_SV_OFF + buf * A_SV_SZ;

        // ---- S (log2-domain) = Q @ K^T ----
        float sacc[8][4];
#pragma unroll
        for (int i = 0; i < 8; i++)
#pragma unroll
            for (int j = 0; j < 4; j++) sacc[i][j] = 0.f;

#pragma unroll
        for (int kt = 0; kt < 5; kt++) {
#pragma unroll
            for (int bp = 0; bp < 4; bp++) {
                uint32_t r0, r1, r2, r3;
                ldmatrix4(r0, r1, r2, r3,
                          bK + (bp * 16 + b_row) * AQ_ROWB + (kt * 16 + b_kof) * 2);
                mma16816(sacc[2 * bp][0], sacc[2 * bp][1],
                         sacc[2 * bp][2], sacc[2 * bp][3],
                         qf[kt][0], qf[kt][1], qf[kt][2], qf[kt][3], r0, r1);
                mma16816(sacc[2 * bp + 1][0], sacc[2 * bp + 1][1],
                         sacc[2 * bp + 1][2], sacc[2 * bp + 1][3],
                         qf[kt][0], qf[kt][1], qf[kt][2], qf[kt][3], r2, r3);
            }
        }

        // ---- max-free softmax: P = exp2(S); partial l sums only ----
        uint32_t pf[4][4];
#pragma unroll
        for (int i = 0; i < 8; i++) {
            sacc[i][0] = ex2(sacc[i][0]);
            sacc[i][1] = ex2(sacc[i][1]);
            sacc[i][2] = ex2(sacc[i][2]);
            sacc[i][3] = ex2(sacc[i][3]);
            l0 += sacc[i][0] + sacc[i][1];
            l1 += sacc[i][2] + sacc[i][3];
        }
#pragma unroll
        for (int kt = 0; kt < 4; kt++) {
            pf[kt][0] = pack_h2(sacc[2 * kt][0],     sacc[2 * kt][1]);
            pf[kt][1] = pack_h2(sacc[2 * kt][2],     sacc[2 * kt][3]);
            pf[kt][2] = pack_h2(sacc[2 * kt + 1][0], sacc[2 * kt + 1][1]);
            pf[kt][3] = pack_h2(sacc[2 * kt + 1][2], sacc[2 * kt + 1][3]);
        }

        // ---- O += P @ V : V row-major [key][d], B fragments via trans ----
#pragma unroll
        for (int kt = 0; kt < 4; kt++) {
#pragma unroll
            for (int bp = 0; bp < 5; bp++) {
                uint32_t r0, r1, r2, r3;
                ldmatrix4_trans(r0, r1, r2, r3,
                                bV + (kt * 16 + tv_row) * AQ_ROWB
                                   + (bp * 16 + tv_n) * 2);
                mma16816(oacc[2 * bp][0], oacc[2 * bp][1],
                         oacc[2 * bp][2], oacc[2 * bp][3],
                         pf[kt][0], pf[kt][1], pf[kt][2], pf[kt][3], r0, r1);
                if (bp < 4)
                    mma16816(oacc[2 * bp + 1][0], oacc[2 * bp + 1][1],
                             oacc[2 * bp + 1][2], oacc[2 * bp + 1][3],
                             pf[kt][0], pf[kt][1], pf[kt][2], pf[kt][3], r2, r3);
            }
        }
    }

    // ---- epilogue: reduce l across the quad, normalize, store ----
    l0 += __shfl_xor_sync(0xffffffffu, l0, 1);
    l0 += __shfl_xor_sync(0xffffffffu, l0, 2);
    l1 += __shfl_xor_sync(0xffffffffu, l1, 1);
    l1 += __shfl_xor_sync(0xffffffffu, l1, 2);
    const float inv0 = 1.f / l0;
    const float inv1 = 1.f / l1;
    const int r = lane >> 2;
    const size_t row0 = rowbase + q0 + warp_m + r;
    const int colb = h * DH + (lane & 3) * 2;
#pragma unroll
    for (int i = 0; i < 9; i++) {
        const int col = colb + i * 8;
        *(uint32_t*)(out + row0 * DMODEL + col) =
            pack_h2(oacc[i][0] * inv0, oacc[i][1] * inv0);
        *(uint32_t*)(out + (row0 + 8) * DMODEL + col) =
            pack_h2(oacc[i][2] * inv1, oacc[i][3] * inv1);
    }
}

// ---------------------------------------------------------------------------
// kernel_launch
// ---------------------------------------------------------------------------
extern "C" void kernel_launch(void* const* d_in, const int* in_sizes, int n_in,
                              void* d_out, int out_size)
{
    const float* hidden = (const float*)d_in[0];
    const float* cosp   = (const float*)d_in[1];
    const float* sinp   = (const float*)d_in[2];
    const float* qkv_w  = (const float*)d_in[3];
    const float* qkv_b  = (const float*)d_in[4];
    const float* proj_w = (const float*)d_in[5];
    const float* proj_b = (const float*)d_in[6];
    (void)in_sizes; (void)n_in;

    __half *qkv_h = nullptr, *hidden_h = nullptr, *qkvw_h = nullptr, *projw_h = nullptr;
    __half *qh = nullptr, *kh = nullptr, *attn_h = nullptr;
    cudaGetSymbolAddress((void**)&qkv_h, g_qkv_h);
    cudaGetSymbolAddress((void**)&hidden_h, g_hidden_h);
    cudaGetSymbolAddress((void**)&qkvw_h, g_qkvw_h);
    cudaGetSymbolAddress((void**)&projw_h, g_projw_h);
    cudaGetSymbolAddress((void**)&qh, g_q_h);
    cudaGetSymbolAddress((void**)&kh, g_k_h);
    cudaGetSymbolAddress((void**)&attn_h, g_attn_h);

    cudaFuncSetAttribute(gemm_f16_kernel<__half>,
                         cudaFuncAttributeMaxDynamicSharedMemorySize, GSM_BYTES);
    cudaFuncSetAttribute(gemm_f16_kernel<float>,
                         cudaFuncAttributeMaxDynamicSharedMemorySize, GSM_BYTES);
    cudaFuncSetAttribute(attn_mma_kernel,
                         cudaFuncAttributeMaxDynamicSharedMemorySize, A_SMEM_BYTES);

    // 0) fp32 -> fp16 conversions (single launch)
    {
        const int ntot = CVT_N1 + CVT_N2 + CVT_N3;
        cvt3_f16_kernel<<<(ntot / 4 + 255) / 256, 256>>>(
            hidden, hidden_h, qkv_w, qkvw_h, proj_w, projw_h);
    }

    // 1) QKV GEMM + bias -> fp16
    gemm_f16_kernel<__half><<<dim3(QKV3 / BN, SQ / BM), 256, GSM_BYTES>>>(
        hidden_h, qkvw_h, qkv_b, qkv_h, SQ, QKV3, DMODEL);

    // 2) RoPE (Q scaled incl. log2e, K) — V untouched
    {
        const int total = SQ * NH * (DH / 2);
        rope_pack_kernel<<<(total + 255) / 256, 256>>>(qkv_h, cosp, sinp, qh, kh);
    }

    // 3) tensor-core flash attention (plain grid, R14 known-good)
    attn_mma_kernel<<<dim3(LCHUNK / 128, NCHUNK * NH), 256, A_SMEM_BYTES>>>(
        qh, kh, qkv_h, attn_h);

    // 4) output projection + bias -> fp32 d_out
    gemm_f16_kernel<float><<<dim3(DMODEL / BN, SQ / BM), 256, GSM_BYTES>>>(
        attn_h, projw_h, proj_b, (float*)d_out, SQ, DMODEL, DMODEL);
}

// round 17
// speedup vs baseline: 1.0364x; 1.0205x over previous
#include <cuda_runtime.h>
#include <cuda_fp16.h>
#include <cstdint>

// Problem constants
#define SQ     8192
#define DMODEL 1152
#define NH     16
#define DH     72
#define QKV3   3456
#define LCHUNK 1024
#define NCHUNK 8

// Scratch (device globals; no cudaMalloc allowed)
__device__ __half g_qkv_h[(size_t)SQ * QKV3];      // fp16 qkv GEMM output (V read from here)
__device__ __half g_hidden_h[(size_t)SQ * DMODEL];
__device__ __half g_qkvw_h[(size_t)QKV3 * DMODEL];
__device__ __half g_projw_h[(size_t)DMODEL * DMODEL];
__device__ __half g_q_h[(size_t)SQ * DMODEL];      // roped Q fp16, scaled by scl*log2(e)
__device__ __half g_k_h[(size_t)SQ * DMODEL];      // roped K fp16
__device__ __half g_attn_h[(size_t)SQ * DMODEL];   // attention output fp16

// ---------------------------------------------------------------------------
// common PTX helpers (cp.async .ca — known-good)
// ---------------------------------------------------------------------------
__device__ __forceinline__ uint32_t smem_u32(const void* p) {
    uint32_t a;
    asm("{ .reg .u64 t; cvta.to.shared.u64 t, %1; cvt.u32.u64 %0, t; }"
        : "=r"(a) : "l"(p));
    return a;
}
__device__ __forceinline__ void cp16(uint32_t dst, const void* src) {
    asm volatile("cp.async.ca.shared.global [%0], [%1], 16;"
                 :: "r"(dst), "l"(src));
}
__device__ __forceinline__ void cp_commit() {
    asm volatile("cp.async.commit_group;");
}
template <int N>
__device__ __forceinline__ void cp_wait() {
    asm volatile("cp.async.wait_group %0;" :: "n"(N));
}
__device__ __forceinline__ void ldmatrix4(uint32_t& r0, uint32_t& r1,
                                          uint32_t& r2, uint32_t& r3,
                                          uint32_t addr) {
    asm volatile("ldmatrix.sync.aligned.m8n8.x4.shared.b16 {%0,%1,%2,%3}, [%4];"
                 : "=r"(r0), "=r"(r1), "=r"(r2), "=r"(r3) : "r"(addr));
}
__device__ __forceinline__ void ldmatrix4_trans(uint32_t& r0, uint32_t& r1,
                                                uint32_t& r2, uint32_t& r3,
                                                uint32_t addr) {
    asm volatile("ldmatrix.sync.aligned.m8n8.x4.trans.shared.b16 {%0,%1,%2,%3}, [%4];"
                 : "=r"(r0), "=r"(r1), "=r"(r2), "=r"(r3) : "r"(addr));
}
__device__ __forceinline__ void mma16816(float& c0, float& c1, float& c2, float& c3,
                                         uint32_t a0, uint32_t a1, uint32_t a2, uint32_t a3,
                                         uint32_t b0, uint32_t b1) {
    asm volatile(
        "mma.sync.aligned.m16n8k16.row.col.f32.f16.f16.f32 "
        "{%0,%1,%2,%3}, {%4,%5,%6,%7}, {%8,%9}, {%0,%1,%2,%3};"
        : "+f"(c0), "+f"(c1), "+f"(c2), "+f"(c3)
        : "r"(a0), "r"(a1), "r"(a2), "r"(a3), "r"(b0), "r"(b1));
}
__device__ __forceinline__ uint32_t pack_h2(float lo, float hi) {
    uint32_t r;
    asm("cvt.rn.f16x2.f32 %0, %1, %2;" : "=r"(r) : "f"(hi), "f"(lo));
    return r;
}
__device__ __forceinline__ float ex2(float x) {
    float y;
    asm("ex2.approx.ftz.f32 %0, %1;" : "=f"(y) : "f"(x));
    return y;
}

// ---------------------------------------------------------------------------
// merged fp32 -> fp16 conversion over three buffers (one launch)
// ---------------------------------------------------------------------------
#define CVT_N1 (SQ * DMODEL)        // hidden     9437184
#define CVT_N2 (QKV3 * DMODEL)      // qkv_w      3981312
#define CVT_N3 (DMODEL * DMODEL)    // proj_w     1327104

__global__ __launch_bounds__(256) void cvt3_f16_kernel(
    const float* __restrict__ in1, __half* __restrict__ out1,
    const float* __restrict__ in2, __half* __restrict__ out2,
    const float* __restrict__ in3, __half* __restrict__ out3)
{
    int i = (blockIdx.x * blockDim.x + threadIdx.x) * 4;
    const float* in;
    __half* out;
    if (i < CVT_N1)                   { in = in1; out = out1; }
    else if (i < CVT_N1 + CVT_N2)     { in = in2; out = out2; i -= CVT_N1; }
    else if (i < CVT_N1 + CVT_N2 + CVT_N3) { in = in3; out = out3; i -= CVT_N1 + CVT_N2; }
    else return;
    const float4 v = *(const float4*)(in + i);
    __half2* o = (__half2*)(out + i);
    o[0] = __floats2half2_rn(v.x, v.y);
    o[1] = __floats2half2_rn(v.z, v.w);
}

// ---------------------------------------------------------------------------
// fp16 tensor-core GEMM (R14 known-good): C = A @ W^T + bias.
// 128x128 tile, BK=64, 2-stage cp.async, 256 threads, 144B smem rows,
// single barrier per slab.
// ---------------------------------------------------------------------------
#define BM 128
#define BN 128
#define BK 64
#define SROW 144
#define G_STAGE (BM * SROW)
#define GSM_BYTES (4 * G_STAGE)

template <typename OutT>
__global__ __launch_bounds__(256) void gemm_f16_kernel(
    const __half* __restrict__ A, const __half* __restrict__ W,
    const float* __restrict__ bias, OutT* __restrict__ C,
    int M, int N, int K)
{
    extern __shared__ unsigned char gsm[];
    const uint32_t sA = smem_u32(gsm);
    const uint32_t sB = sA + 2 * G_STAGE;

    const int tid  = threadIdx.x;
    const int wid  = tid >> 5;
    const int lane = tid & 31;
    const int bm = blockIdx.y * BM;
    const int bn = blockIdx.x * BN;

    const int warp_m = (wid >> 2) * 64;
    const int warp_n = (wid & 3) * 32;

    const int nslab = K / BK;

    auto load_stage = [&](int buf, int k0) {
#pragma unroll
        for (int u = 0; u < 4; u++) {
            const int c = tid + u * 256;
            const int row = c >> 3, col = c & 7;
            cp16(sA + buf * G_STAGE + row * SROW + col * 16,
                 A + (size_t)(bm + row) * K + k0 + col * 8);
            cp16(sB + buf * G_STAGE + row * SROW + col * 16,
                 W + (size_t)(bn + row) * K + k0 + col * 8);
        }
        cp_commit();
    };

    load_stage(0, 0);

    float acc[4][4][4];
#pragma unroll
    for (int i = 0; i < 4; i++)
#pragma unroll
        for (int j = 0; j < 4; j++)
#pragma unroll
            for (int v = 0; v < 4; v++) acc[i][j][v] = 0.f;

    const int a_row = lane & 15;
    const int a_kof = (lane >> 4) * 8;
    const int b_row = ((lane >> 4) * 8) + (lane & 7);
    const int b_kof = ((lane >> 3) & 1) * 8;

    for (int s = 0; s < nslab; s++) {
        const int buf = s & 1;
        cp_wait<0>();
        __syncthreads();

        if (s + 1 < nslab)
            load_stage((s + 1) & 1, (s + 1) * BK);

        const uint32_t bA = sA + buf * G_STAGE;
        const uint32_t bB = sB + buf * G_STAGE;

#pragma unroll
        for (int ks = 0; ks < 4; ks++) {
            uint32_t af[4][4];
#pragma unroll
            for (int mt = 0; mt < 4; mt++)
                ldmatrix4(af[mt][0], af[mt][1], af[mt][2], af[mt][3],
                          bA + (warp_m + mt * 16 + a_row) * SROW
                             + (ks * 16 + a_kof) * 2);
            uint32_t bf[4][2];
#pragma unroll
            for (int nt2 = 0; nt2 < 2; nt2++) {
                uint32_t r0, r1, r2, r3;
                ldmatrix4(r0, r1, r2, r3,
                          bB + (warp_n + nt2 * 16 + b_row) * SROW
                             + (ks * 16 + b_kof) * 2);
                bf[nt2 * 2 + 0][0] = r0; bf[nt2 * 2 + 0][1] = r1;
                bf[nt2 * 2 + 1][0] = r2; bf[nt2 * 2 + 1][1] = r3;
            }
#pragma unroll
            for (int mt = 0; mt < 4; mt++)
#pragma unroll
                for (int nt = 0; nt < 4; nt++)
                    mma16816(acc[mt][nt][0], acc[mt][nt][1],
                             acc[mt][nt][2], acc[mt][nt][3],
                             af[mt][0], af[mt][1], af[mt][2], af[mt][3],
                             bf[nt][0], bf[nt][1]);
        }
    }

    const int erow = lane >> 2;
    const int ecol = (lane & 3) * 2;
#pragma unroll
    for (int mt = 0; mt < 4; mt++) {
#pragma unroll
        for (int nt = 0; nt < 4; nt++) {
            const int col = bn + warp_n + nt * 8 + ecol;
            const float b0 = bias[col], b1 = bias[col + 1];
            const size_t r0 = (size_t)(bm + warp_m + mt * 16 + erow);
            if constexpr (sizeof(OutT) == 2) {
                *(uint32_t*)((__half*)C + r0 * N + col) =
                    pack_h2(acc[mt][nt][0] + b0, acc[mt][nt][1] + b1);
                *(uint32_t*)((__half*)C + (r0 + 8) * N + col) =
                    pack_h2(acc[mt][nt][2] + b0, acc[mt][nt][3] + b1);
            } else {
                *(float2*)((float*)C + r0 * N + col) =
                    make_float2(acc[mt][nt][0] + b0, acc[mt][nt][1] + b1);
                *(float2*)((float*)C + (r0 + 8) * N + col) =
                    make_float2(acc[mt][nt][2] + b0, acc[mt][nt][3] + b1);
            }
        }
    }
}

// ---------------------------------------------------------------------------
// RoPE: Q scaled by (1/sqrt(DH)) * log2(e); K unscaled. V untouched.
// ---------------------------------------------------------------------------
__global__ __launch_bounds__(256) void rope_pack_kernel(
    const __half* __restrict__ qkv, const float* __restrict__ cosp,
    const float* __restrict__ sinp,
    __half* __restrict__ qh, __half* __restrict__ kh)
{
    const int idx = blockIdx.x * blockDim.x + threadIdx.x;
    const int total = SQ * NH * (DH / 2);
    if (idx >= total) return;
    const int d = idx % (DH / 2);
    const int t = idx / (DH / 2);
    const int h = t % NH;
    const int s = t / NH;

    const float c1 = cosp[s * DH + d];
    const float s1 = sinp[s * DH + d];
    const float c2 = cosp[s * DH + d + 36];
    const float s2 = sinp[s * DH + d + 36];
    const float scl = rsqrtf((float)DH) * 1.4426950408889634f;  // fold log2(e)

    const size_t base = (size_t)s * QKV3 + h * DH;
    {
        const float x1 = __half2float(qkv[base + d]);
        const float x2 = __half2float(qkv[base + d + 36]);
        qh[(size_t)s * DMODEL + h * DH + d]      = __float2half_rn((x1 * c1 - x2 * s1) * scl);
        qh[(size_t)s * DMODEL + h * DH + d + 36] = __float2half_rn((x2 * c2 + x1 * s2) * scl);
    }
    {
        const float x1 = __half2float(qkv[base + DMODEL + d]);
        const float x2 = __half2float(qkv[base + DMODEL + d + 36]);
        kh[(size_t)s * DMODEL + h * DH + d]      = __float2half_rn(x1 * c1 - x2 * s1);
        kh[(size_t)s * DMODEL + h * DH + d + 36] = __float2half_rn(x2 * c2 + x1 * s2);
    }
}

// ---------------------------------------------------------------------------
// Tensor-core flash attention (R16 + strength-reduced loader):
// each thread's <=5 cp.async slots (smem offset, global ptr, stride) are
// precomputed ONCE; per tile the loader is 5 predicated cp.async + ptr adds.
// K and V stage sizes are equal so one nbuf*A_SK_SZ term serves both.
// __launch_bounds__(256,2) pins 2 CTAs/SM (regs <= 128).
// smem: sQ 128x176 + sK 2x64x176 + sV 2x64x176 = 67584 B.
// ---------------------------------------------------------------------------
#define AQ_ROWB  176
#define A_SQ_OFF  0
#define A_SK_OFF  (128 * AQ_ROWB)                 // 22528
#define A_SK_SZ   (64 * AQ_ROWB)                  // 11264
#define A_SV_OFF  (A_SK_OFF + 2 * A_SK_SZ)        // 45056
#define A_SV_SZ   (64 * AQ_ROWB)                  // 11264
#define A_SMEM_BYTES (A_SV_OFF + 2 * A_SV_SZ)     // 67584

__global__ __launch_bounds__(256, 2) void attn_mma_kernel(
    const __half* __restrict__ Qg, const __half* __restrict__ Kg,
    const __half* __restrict__ qkv, __half* __restrict__ out)
{
    extern __shared__ unsigned char asmem[];
    const uint32_t sb = smem_u32(asmem);
    const int tid  = threadIdx.x;
    const int wid  = tid >> 5;
    const int lane = tid & 31;
    const int qt  = blockIdx.x;
    const int chh = blockIdx.y;
    const int chunk = chh >> 4, h = chh & 15;
    const size_t rowbase = (size_t)chunk * LCHUNK;
    const int q0 = qt * 128;
    const int warp_m = wid * 16;

    // V source: [S, 3, H, DH] slab 2
    const __half* Vg = qkv + 2 * DMODEL + h * DH;

    // ---- zero pads (d columns 72..79 of sQ, sK, sV) ----
    const uint4 z4 = make_uint4(0, 0, 0, 0);
    if (tid < 128) {
        *(uint4*)(asmem + A_SQ_OFF + tid * AQ_ROWB + 144) = z4;
        const int buf = tid >> 6, row = tid & 63;
        *(uint4*)(asmem + A_SK_OFF + buf * A_SK_SZ + row * AQ_ROWB + 144) = z4;
    } else {
        const int t = tid - 128;
        const int buf = t >> 6, row = t & 63;
        *(uint4*)(asmem + A_SV_OFF + buf * A_SV_SZ + row * AQ_ROWB + 144) = z4;
    }

    // ---- strength-reduced loader state: <=5 slots per thread, hoisted ----
    uint32_t soff[5];          // smem offset for buf 0 (add nbuf*A_SK_SZ)
    const __half* gp[5];       // current global pointer
    int ginc[5];               // elements to advance per 64-key tile
#pragma unroll
    for (int j = 0; j < 5; j++) {
        const int i = tid + j * 256;
        if (i < 1152) {
            if (i < 576) {
                const int row = i / 9, c = i % 9;
                soff[j] = A_SK_OFF + row * AQ_ROWB + c * 16;
                gp[j]   = Kg + (rowbase + row) * DMODEL + h * DH + c * 8;
                ginc[j] = 64 * DMODEL;
            } else {
                const int jj = i - 576;
                const int row = jj / 9, c = jj % 9;
                soff[j] = A_SV_OFF + row * AQ_ROWB + c * 16;
                gp[j]   = Vg + (rowbase + row) * QKV3 + c * 8;
                ginc[j] = 64 * QKV3;
            }
        }
    }
    const bool has5 = (tid < 128);   // slot 4 valid only for tid < 128

    auto load_tile = [&](int nbuf) {
        const uint32_t bo = sb + nbuf * A_SK_SZ;
#pragma unroll
        for (int j = 0; j < 4; j++) {
            cp16(bo + soff[j], gp[j]);
            gp[j] += ginc[j];
        }
        if (has5) {
            cp16(bo + soff[4], gp[4]);
            gp[4] += ginc[4];
        }
        cp_commit();
    };

    // ---- prologue: Q tile + key tile 0 (one group) ----
    for (int i = tid; i < 128 * 9; i += 256) {
        const int row = i / 9, c = i % 9;
        cp16(sb + A_SQ_OFF + row * AQ_ROWB + c * 16,
             Qg + (rowbase + q0 + row) * DMODEL + h * DH + c * 8);
    }
    load_tile(0);

    const int a_row = lane & 15;
    const int a_kof = (lane >> 4) * 8;
    const int b_row = ((lane >> 4) * 8) + (lane & 7);
    const int b_kof = ((lane >> 3) & 1) * 8;
    const int tv_row = ((lane >> 3) & 1) * 8 + (lane & 7);
    const int tv_n   = (lane >> 4) * 8;

    uint32_t qf[5][4];
    float oacc[9][4];
#pragma unroll
    for (int i = 0; i < 9; i++)
#pragma unroll
        for (int j = 0; j < 4; j++) oacc[i][j] = 0.f;
    float l0 = 0.f, l1 = 0.f;

    const int NTILE = LCHUNK / 64;   // 16

    for (int t = 0; t < NTILE; t++) {
        const int buf = t & 1;
        cp_wait<0>();
        __syncthreads();

        if (t + 1 < NTILE)
            load_tile((t + 1) & 1);

        if (t == 0) {
#pragma unroll
            for (int kt = 0; kt < 5; kt++)
                ldmatrix4(qf[kt][0], qf[kt][1], qf[kt][2], qf[kt][3],
                          sb + A_SQ_OFF + (warp_m + a_row) * AQ_ROWB
                             + (kt * 16 + a_kof) * 2);
        }

        const uint32_t bK = sb + buf * A_SK_SZ + A_SK_OFF;
        const uint32_t bV = sb + buf * A_SV_SZ + A_SV_OFF;

        // ---- S (log2-domain) = Q @ K^T ----
        float sacc[8][4];
#pragma unroll
        for (int i = 0; i < 8; i++)
#pragma unroll
            for (int j = 0; j < 4; j++) sacc[i][j] = 0.f;

#pragma unroll
        for (int kt = 0; kt < 5; kt++) {
#pragma unroll
            for (int bp = 0; bp < 4; bp++) {
                uint32_t r0, r1, r2, r3;
                ldmatrix4(r0, r1, r2, r3,
                          bK + (bp * 16 + b_row) * AQ_ROWB + (kt * 16 + b_kof) * 2);
                mma16816(sacc[2 * bp][0], sacc[2 * bp][1],
                         sacc[2 * bp][2], sacc[2 * bp][3],
                         qf[kt][0], qf[kt][1], qf[kt][2], qf[kt][3], r0, r1);
                mma16816(sacc[2 * bp + 1][0], sacc[2 * bp + 1][1],
                         sacc[2 * bp + 1][2], sacc[2 * bp + 1][3],
                         qf[kt][0], qf[kt][1], qf[kt][2], qf[kt][3], r2, r3);
            }
        }

        // ---- max-free softmax: P = exp2(S); partial l sums only ----
        uint32_t pf[4][4];
#pragma unroll
        for (int i = 0; i < 8; i++) {
            sacc[i][0] = ex2(sacc[i][0]);
            sacc[i][1] = ex2(sacc[i][1]);
            sacc[i][2] = ex2(sacc[i][2]);
            sacc[i][3] = ex2(sacc[i][3]);
            l0 += sacc[i][0] + sacc[i][1];
            l1 += sacc[i][2] + sacc[i][3];
        }
#pragma unroll
        for (int kt = 0; kt < 4; kt++) {
            pf[kt][0] = pack_h2(sacc[2 * kt][0],     sacc[2 * kt][1]);
            pf[kt][1] = pack_h2(sacc[2 * kt][2],     sacc[2 * kt][3]);
            pf[kt][2] = pack_h2(sacc[2 * kt + 1][0], sacc[2 * kt + 1][1]);
            pf[kt][3] = pack_h2(sacc[2 * kt + 1][2], sacc[2 * kt + 1][3]);
        }

        // ---- O += P @ V : V row-major [key][d], B fragments via trans ----
#pragma unroll
        for (int kt = 0; kt < 4; kt++) {
#pragma unroll
            for (int bp = 0; bp < 5; bp++) {
                uint32_t r0, r1, r2, r3;
                ldmatrix4_trans(r0, r1, r2, r3,
                                bV + (kt * 16 + tv_row) * AQ_ROWB
                                   + (bp * 16 + tv_n) * 2);
                mma16816(oacc[2 * bp][0], oacc[2 * bp][1],
                         oacc[2 * bp][2], oacc[2 * bp][3],
                         pf[kt][0], pf[kt][1], pf[kt][2], pf[kt][3], r0, r1);
                if (bp < 4)
                    mma16816(oacc[2 * bp + 1][0], oacc[2 * bp + 1][1],
                             oacc[2 * bp + 1][2], oacc[2 * bp + 1][3],
                             pf[kt][0], pf[kt][1], pf[kt][2], pf[kt][3], r2, r3);
            }
        }
    }

    // ---- epilogue: reduce l across the quad, normalize, store ----
    l0 += __shfl_xor_sync(0xffffffffu, l0, 1);
    l0 += __shfl_xor_sync(0xffffffffu, l0, 2);
    l1 += __shfl_xor_sync(0xffffffffu, l1, 1);
    l1 += __shfl_xor_sync(0xffffffffu, l1, 2);
    const float inv0 = 1.f / l0;
    const float inv1 = 1.f / l1;
    const int r = lane >> 2;
    const size_t row0 = rowbase + q0 + warp_m + r;
    const int colb = h * DH + (lane & 3) * 2;
#pragma unroll
    for (int i = 0; i < 9; i++) {
        const int col = colb + i * 8;
        *(uint32_t*)(out + row0 * DMODEL + col) =
            pack_h2(oacc[i][0] * inv0, oacc[i][1] * inv0);
        *(uint32_t*)(out + (row0 + 8) * DMODEL + col) =
            pack_h2(oacc[i][2] * inv1, oacc[i][3] * inv1);
    }
}

// ---------------------------------------------------------------------------
// kernel_launch
// ---------------------------------------------------------------------------
extern "C" void kernel_launch(void* const* d_in, const int* in_sizes, int n_in,
                              void* d_out, int out_size)
{
    const float* hidden = (const float*)d_in[0];
    const float* cosp   = (const float*)d_in[1];
    const float* sinp   = (const float*)d_in[2];
    const float* qkv_w  = (const float*)d_in[3];
    const float* qkv_b  = (const float*)d_in[4];
    const float* proj_w = (const float*)d_in[5];
    const float* proj_b = (const float*)d_in[6];
    (void)in_sizes; (void)n_in;

    __half *qkv_h = nullptr, *hidden_h = nullptr, *qkvw_h = nullptr, *projw_h = nullptr;
    __half *qh = nullptr, *kh = nullptr, *attn_h = nullptr;
    cudaGetSymbolAddress((void**)&qkv_h, g_qkv_h);
    cudaGetSymbolAddress((void**)&hidden_h, g_hidden_h);
    cudaGetSymbolAddress((void**)&qkvw_h, g_qkvw_h);
    cudaGetSymbolAddress((void**)&projw_h, g_projw_h);
    cudaGetSymbolAddress((void**)&qh, g_q_h);
    cudaGetSymbolAddress((void**)&kh, g_k_h);
    cudaGetSymbolAddress((void**)&attn_h, g_attn_h);

    cudaFuncSetAttribute(gemm_f16_kernel<__half>,
                         cudaFuncAttributeMaxDynamicSharedMemorySize, GSM_BYTES);
    cudaFuncSetAttribute(gemm_f16_kernel<float>,
                         cudaFuncAttributeMaxDynamicSharedMemorySize, GSM_BYTES);
    cudaFuncSetAttribute(attn_mma_kernel,
                         cudaFuncAttributeMaxDynamicSharedMemorySize, A_SMEM_BYTES);

    // 0) fp32 -> fp16 conversions (single launch)
    {
        const int ntot = CVT_N1 + CVT_N2 + CVT_N3;
        cvt3_f16_kernel<<<(ntot / 4 + 255) / 256, 256>>>(
            hidden, hidden_h, qkv_w, qkvw_h, proj_w, projw_h);
    }

    // 1) QKV GEMM + bias -> fp16
    gemm_f16_kernel<__half><<<dim3(QKV3 / BN, SQ / BM), 256, GSM_BYTES>>>(
        hidden_h, qkvw_h, qkv_b, qkv_h, SQ, QKV3, DMODEL);

    // 2) RoPE (Q scaled incl. log2e, K) — V untouched
    {
        const int total = SQ * NH * (DH / 2);
        rope_pack_kernel<<<(total + 255) / 256, 256>>>(qkv_h, cosp, sinp, qh, kh);
    }

    // 3) tensor-core flash attention (strength-reduced loader)
    attn_mma_kernel<<<dim3(LCHUNK / 128, NCHUNK * NH), 256, A_SMEM_BYTES>>>(
        qh, kh, qkv_h, attn_h);

    // 4) output projection + bias -> fp32 d_out
    gemm_f16_kernel<float><<<dim3(DMODEL / BN, SQ / BM), 256, GSM_BYTES>>>(
        attn_h, projw_h, proj_b, (float*)d_out, SQ, DMODEL, DMODEL);
}